// round 14
// baseline (speedup 1.0000x reference)
#include <cuda_runtime.h>
#include <cuda_bf16.h>
#include <cstdint>

#define N_NODES 50000
#define IN_C    256
#define HID     128
#define N_EDGES 800000
#define SCAN_B  256
#define SCAN_NB ((N_NODES + SCAN_B - 1) / SCAN_B)   // 196

// ---- device scratch: referenced ONLY from device code ----
__device__ float g_hs[N_NODES * HID];      // h = x @ W_conv (raw)
__device__ int   g_count[N_NODES];
__device__ int   g_rowptr[N_NODES + 1];
__device__ int   g_cursor[N_NODES];
__device__ int   g_col[N_EDGES];
__device__ float g_dinv[N_NODES];
__device__ float g_bias2[IN_C];
__device__ int   g_blocksum[SCAN_NB];
__device__ __nv_bfloat16 g_wchi[HID * IN_C];   // W_conv^T [n][k]
__device__ __nv_bfloat16 g_wclo[HID * IN_C];
__device__ __nv_bfloat16 g_wlhi[IN_C * HID];   // W_lin^T  [n][k]
__device__ __nv_bfloat16 g_wllo[IN_C * HID];

// ================= helpers =================
__device__ __forceinline__ uint32_t pack_bf16(float a, float b) {
    __nv_bfloat16 ha = __float2bfloat16(a);
    __nv_bfloat16 hb = __float2bfloat16(b);
    uint16_t ua = *reinterpret_cast<uint16_t*>(&ha);
    uint16_t ub = *reinterpret_cast<uint16_t*>(&hb);
    return (uint32_t)ua | ((uint32_t)ub << 16);
}
__device__ __forceinline__ float bf16_residual(float v) {
    __nv_bfloat16 h = __float2bfloat16(v);
    return v - __bfloat162float(h);
}
__device__ __forceinline__ void mma_bf16(float& c0, float& c1, float& c2, float& c3,
                                         uint32_t a0, uint32_t a1, uint32_t a2, uint32_t a3,
                                         uint32_t b0, uint32_t b1) {
    asm volatile(
        "mma.sync.aligned.m16n8k16.row.col.f32.bf16.bf16.f32 "
        "{%0,%1,%2,%3}, {%4,%5,%6,%7}, {%8,%9}, {%0,%1,%2,%3};"
        : "+f"(c0), "+f"(c1), "+f"(c2), "+f"(c3)
        : "r"(a0), "r"(a1), "r"(a2), "r"(a3), "r"(b0), "r"(b1));
}
__device__ __forceinline__ uint32_t smem_addr_u32(const void* p) {
    uint32_t a;
    asm("{ .reg .u64 t; cvta.to.shared.u64 t, %1; cvt.u32.u64 %0, t; }" : "=r"(a) : "l"(p));
    return a;
}
__device__ __forceinline__ void ldmx4(uint32_t& r0, uint32_t& r1, uint32_t& r2, uint32_t& r3,
                                      uint32_t addr) {
    asm volatile("ldmatrix.sync.aligned.m8n8.x4.shared.b16 {%0,%1,%2,%3}, [%4];"
                 : "=r"(r0), "=r"(r1), "=r"(r2), "=r"(r3) : "r"(addr));
}

// ================= prep =================
__global__ void k_prep1(const float* __restrict__ W_conv) {   // W_conv split + zero count
    for (int i = blockIdx.x * blockDim.x + threadIdx.x; i < IN_C * HID;
         i += gridDim.x * blockDim.x) {
        int k = i / HID, n = i % HID;
        float v = W_conv[i];
        g_wchi[n * IN_C + k] = __float2bfloat16(v);
        g_wclo[n * IN_C + k] = __float2bfloat16(bf16_residual(v));
    }
    for (int i = blockIdx.x * blockDim.x + threadIdx.x; i < N_NODES;
         i += gridDim.x * blockDim.x)
        g_count[i] = 0;
}

__global__ void k_prep2(const float* __restrict__ W_lin,      // W_lin split + bias2
                        const float* __restrict__ b_conv,
                        const float* __restrict__ b_lin) {
    int gt = blockIdx.x * blockDim.x + threadIdx.x;
    for (int i = gt; i < HID * IN_C; i += gridDim.x * blockDim.x) {
        int k = i / IN_C, n = i % IN_C;
        float v = W_lin[i];
        g_wlhi[n * HID + k] = __float2bfloat16(v);
        g_wllo[n * HID + k] = __float2bfloat16(bf16_residual(v));
    }
    if (gt < IN_C) {
        float s = b_lin[gt];
        #pragma unroll 4
        for (int k = 0; k < HID; k++) s += b_conv[k] * W_lin[k * IN_C + gt];
        g_bias2[gt] = s;
    }
}

// ================= GEMM1: 1024 threads, A in registers, barrier-free loop =================
#define W_STRIDE 264                         // bf16 per W smem row (528B)
#define SW_HI    0
#define SW_LO    (HID * W_STRIDE * 2)        // 67584
#define G1_SMEM  (2 * HID * W_STRIDE * 2)    // 135168

__global__ __launch_bounds__(1024, 1)
void gemm1_mma(const float* __restrict__ x) {
    extern __shared__ char smem[];
    const uint32_t sb = smem_addr_u32(smem);
    const int tid  = threadIdx.x;
    const int wid  = tid >> 5;        // 0..31
    const int lane = tid & 31;
    const int g    = lane >> 2;
    const int tg   = lane & 3;
    const int wm   = wid >> 2;        // 0..7 -> 16-row strip
    const int wn   = wid & 3;         // 0..3 -> 32-col strip
    const int rowBase = blockIdx.x * 128;

    // stage W^T hi/lo (once)
    for (int idx = tid; idx < 128 * 32; idx += 1024) {
        int n = idx >> 5;
        int q = idx & 31;
        *reinterpret_cast<uint4*>(smem + SW_HI + n * (W_STRIDE * 2) + q * 16) =
            *reinterpret_cast<const uint4*>(&g_wchi[n * IN_C + q * 8]);
        *reinterpret_cast<uint4*>(smem + SW_LO + n * (W_STRIDE * 2) + q * 16) =
            *reinterpret_cast<const uint4*>(&g_wclo[n * IN_C + q * 8]);
    }

    // ---- B ldmatrix per-thread addresses ----
    const int lj = lane >> 3;                 // matrix index 0..3
    const int lr = lane & 7;                  // row within matrix
    uint32_t bAddr[2];
    #pragma unroll
    for (int p = 0; p < 2; p++)
        bAddr[p] = sb + SW_HI +
            (uint32_t)((wn * 32 + p * 16 + (lj >> 1) * 8 + lr) * (W_STRIDE * 2) +
                       (lj & 1) * 16);

    // ---- A register-direct identity ----
    const int row0 = rowBase + wm * 16 + g;
    const int row1 = row0 + 8;
    const bool v0 = (row0 < N_NODES);
    const bool v1 = (row1 < N_NODES);
    const float* a0p = x + (size_t)row0 * IN_C + tg * 2;
    const float* a1p = x + (size_t)row1 * IN_C + tg * 2;

    float c[4][4];
    #pragma unroll
    for (int nt = 0; nt < 4; nt++)
        #pragma unroll
        for (int q = 0; q < 4; q++) c[nt][q] = 0.0f;

    __syncthreads();    // W staged; loop below has no barriers

    #pragma unroll 4
    for (int kc = 0; kc < 16; kc++) {
        const int k0 = kc * 16;
        float2 f00 = make_float2(0.f, 0.f), f01 = f00, f10 = f00, f11 = f00;
        if (v0) {
            f00 = *reinterpret_cast<const float2*>(a0p + k0);
            f01 = *reinterpret_cast<const float2*>(a0p + k0 + 8);
        }
        if (v1) {
            f10 = *reinterpret_cast<const float2*>(a1p + k0);
            f11 = *reinterpret_cast<const float2*>(a1p + k0 + 8);
        }
        uint32_t ah[4], al[4];
        ah[0] = pack_bf16(f00.x, f00.y);
        ah[1] = pack_bf16(f10.x, f10.y);
        ah[2] = pack_bf16(f01.x, f01.y);
        ah[3] = pack_bf16(f11.x, f11.y);
        al[0] = pack_bf16(bf16_residual(f00.x), bf16_residual(f00.y));
        al[1] = pack_bf16(bf16_residual(f10.x), bf16_residual(f10.y));
        al[2] = pack_bf16(bf16_residual(f01.x), bf16_residual(f01.y));
        al[3] = pack_bf16(bf16_residual(f11.x), bf16_residual(f11.y));

        #pragma unroll
        for (int pr = 0; pr < 2; pr++) {
            uint32_t bh[4], bl[4];
            uint32_t ba = bAddr[pr] + (uint32_t)(kc * 32);
            ldmx4(bh[0], bh[1], bh[2], bh[3], ba);
            ldmx4(bl[0], bl[1], bl[2], bl[3], ba + (uint32_t)(SW_LO - SW_HI));
            #pragma unroll
            for (int s = 0; s < 2; s++) {
                int nt = pr * 2 + s;
                mma_bf16(c[nt][0], c[nt][1], c[nt][2], c[nt][3],
                         ah[0], ah[1], ah[2], ah[3], bh[s * 2], bh[s * 2 + 1]);
                mma_bf16(c[nt][0], c[nt][1], c[nt][2], c[nt][3],
                         ah[0], ah[1], ah[2], ah[3], bl[s * 2], bl[s * 2 + 1]);
                mma_bf16(c[nt][0], c[nt][1], c[nt][2], c[nt][3],
                         al[0], al[1], al[2], al[3], bh[s * 2], bh[s * 2 + 1]);
            }
        }
    }

    // epilogue
    {
        #pragma unroll
        for (int nt = 0; nt < 4; nt++) {
            int col = wn * 32 + nt * 8 + tg * 2;
            if (v0)
                *reinterpret_cast<float2*>(&g_hs[(size_t)row0 * HID + col]) =
                    make_float2(c[nt][0], c[nt][1]);
            if (v1)
                *reinterpret_cast<float2*>(&g_hs[(size_t)row1 * HID + col]) =
                    make_float2(c[nt][2], c[nt][3]);
        }
    }
}

// ================= CSR build =================
__global__ void k_count(const int* __restrict__ dst) {
    for (int e = blockIdx.x * blockDim.x + threadIdx.x; e < N_EDGES;
         e += gridDim.x * blockDim.x)
        atomicAdd(&g_count[dst[e]], 1);
}

__global__ void k_scan1() {
    __shared__ int sh[SCAN_B];
    int i = blockIdx.x * SCAN_B + threadIdx.x;
    int v = (i < N_NODES) ? g_count[i] : 0;
    sh[threadIdx.x] = v;
    __syncthreads();
    #pragma unroll
    for (int o = 1; o < SCAN_B; o <<= 1) {
        int t = (threadIdx.x >= o) ? sh[threadIdx.x - o] : 0;
        __syncthreads();
        sh[threadIdx.x] += t;
        __syncthreads();
    }
    if (i < N_NODES) g_rowptr[i] = sh[threadIdx.x] - v;
    if (threadIdx.x == SCAN_B - 1) g_blocksum[blockIdx.x] = sh[SCAN_B - 1];
}

__global__ void k_scan3m() {
    __shared__ int sh[256];
    const int bid = blockIdx.x;
    const int t = threadIdx.x;
    sh[t] = (t < SCAN_NB && t < bid) ? g_blocksum[t] : 0;
    __syncthreads();
    #pragma unroll
    for (int s = 128; s > 0; s >>= 1) {
        if (t < s) sh[t] += sh[t + s];
        __syncthreads();
    }
    const int off = sh[0];
    int i = bid * SCAN_B + t;
    if (i < N_NODES) {
        int r = g_rowptr[i] + off;
        g_rowptr[i] = r;
        g_cursor[i] = r;
        g_dinv[i]   = rsqrtf((float)(g_count[i] + 1));
    }
    if (bid == 0 && t == 0) g_rowptr[N_NODES] = N_EDGES;
}

__global__ void k_fill(const int* __restrict__ src, const int* __restrict__ dst) {
    for (int e = blockIdx.x * blockDim.x + threadIdx.x; e < N_EDGES;
         e += gridDim.x * blockDim.x) {
        int p = atomicAdd(&g_cursor[dst[e]], 1);
        g_col[p] = src[e];
    }
}

// ================= FUSED gather + HMMA GEMM2 (ldmatrix frags) =================
#define F2_PAD   272
#define F2_WPAD  144
#define F2_SA_HI 0
#define F2_SA_LO (64 * F2_PAD)                  // 17408
#define F2_SW_HI (2 * 64 * F2_PAD)              // 34816
#define F2_SW_LO (F2_SW_HI + 256 * F2_WPAD)     // 71680
#define F2_SMEM  (F2_SW_LO + 256 * F2_WPAD)     // 108544

__global__ __launch_bounds__(512, 2)
void k_fused2(float* __restrict__ out) {
    extern __shared__ char smem[];
    const uint32_t sb = smem_addr_u32(smem);
    const int tid = threadIdx.x;
    const int w   = tid >> 5;
    const int l   = tid & 31;
    const int rowBase = blockIdx.x * 64;

    // ---- gather 64 nodes (4 per warp) ----
    const float4* hs4 = reinterpret_cast<const float4*>(g_hs);
    #pragma unroll
    for (int q = 0; q < 4; q++) {
        int nLocal = q * 16 + w;
        int i = rowBase + nLocal;
        float4 acc = make_float4(0.f, 0.f, 0.f, 0.f);
        if (i < N_NODES) {
            float di = g_dinv[i];
            float4 v = hs4[(size_t)i * 32 + l];
            acc.x = v.x * di; acc.y = v.y * di; acc.z = v.z * di; acc.w = v.w * di;
            int e  = g_rowptr[i];
            int e1 = g_rowptr[i + 1];
            for (; e + 2 <= e1; e += 2) {
                int j0 = g_col[e];
                int j1 = g_col[e + 1];
                float d0 = g_dinv[j0];
                float d1 = g_dinv[j1];
                float4 u0 = hs4[(size_t)j0 * 32 + l];
                float4 u1 = hs4[(size_t)j1 * 32 + l];
                acc.x += u0.x * d0 + u1.x * d1;
                acc.y += u0.y * d0 + u1.y * d1;
                acc.z += u0.z * d0 + u1.z * d1;
                acc.w += u0.w * d0 + u1.w * d1;
            }
            if (e < e1) {
                int j = g_col[e];
                float dj = g_dinv[j];
                float4 u = hs4[(size_t)j * 32 + l];
                acc.x += u.x * dj; acc.y += u.y * dj;
                acc.z += u.z * dj; acc.w += u.w * dj;
            }
            acc.x *= di; acc.y *= di; acc.z *= di; acc.w *= di;
        }
        uint2 hi, lo;
        hi.x = pack_bf16(acc.x, acc.y);
        hi.y = pack_bf16(acc.z, acc.w);
        lo.x = pack_bf16(bf16_residual(acc.x), bf16_residual(acc.y));
        lo.y = pack_bf16(bf16_residual(acc.z), bf16_residual(acc.w));
        *reinterpret_cast<uint2*>(smem + F2_SA_HI + nLocal * F2_PAD + l * 8) = hi;
        *reinterpret_cast<uint2*>(smem + F2_SA_LO + nLocal * F2_PAD + l * 8) = lo;
    }
    __syncthreads();

    // ---- HMMA: out[64,256] = agg @ W_lin, K split into two 64-wide passes ----
    const int g  = l >> 2;
    const int tg = l & 3;
    const int wm = w >> 3;            // 0..1
    const int wn = w & 7;             // 0..7
    const int lj = l >> 3;
    const int lr = l & 7;

    // ldmatrix base addresses
    const uint32_t aAddrF = sb + F2_SA_HI +
        (uint32_t)((wm * 32 + (lj & 1) * 8 + lr) * F2_PAD + (lj >> 1) * 16);
    uint32_t bAddrF[2];
    #pragma unroll
    for (int p = 0; p < 2; p++)
        bAddrF[p] = sb + F2_SW_HI +
            (uint32_t)((wn * 32 + p * 16 + (lj >> 1) * 8 + lr) * F2_WPAD + (lj & 1) * 16);

    float c[2][4][4];
    #pragma unroll
    for (int mt = 0; mt < 2; mt++)
        #pragma unroll
        for (int nt = 0; nt < 4; nt++)
            #pragma unroll
            for (int q = 0; q < 4; q++) c[mt][nt][q] = 0.0f;

    #pragma unroll
    for (int pass = 0; pass < 2; pass++) {
        for (int idx = tid; idx < 256 * 8; idx += 512) {
            int n  = idx >> 3;
            int q8 = idx & 7;
            *reinterpret_cast<uint4*>(smem + F2_SW_HI + n * F2_WPAD + q8 * 16) =
                *reinterpret_cast<const uint4*>(&g_wlhi[n * HID + pass * 64 + q8 * 8]);
            *reinterpret_cast<uint4*>(smem + F2_SW_LO + n * F2_WPAD + q8 * 16) =
                *reinterpret_cast<const uint4*>(&g_wllo[n * HID + pass * 64 + q8 * 8]);
        }
        __syncthreads();

        #pragma unroll
        for (int kc = 0; kc < 4; kc++) {
            // B fragments for all 4 nt (hi+lo), loaded once per kc
            uint32_t bh[8], bl[8];
            #pragma unroll
            for (int pr = 0; pr < 2; pr++) {
                uint32_t ba = bAddrF[pr] + (uint32_t)(kc * 32);
                ldmx4(bh[pr * 4 + 0], bh[pr * 4 + 1], bh[pr * 4 + 2], bh[pr * 4 + 3], ba);
                ldmx4(bl[pr * 4 + 0], bl[pr * 4 + 1], bl[pr * 4 + 2], bl[pr * 4 + 3],
                      ba + (uint32_t)(F2_SW_LO - F2_SW_HI));
            }
            #pragma unroll
            for (int mt = 0; mt < 2; mt++) {
                uint32_t aa = aAddrF + (uint32_t)(mt * 16 * F2_PAD + pass * 128 + kc * 32);
                uint32_t ah[4], al[4];
                ldmx4(ah[0], ah[1], ah[2], ah[3], aa);
                ldmx4(al[0], al[1], al[2], al[3], aa + (uint32_t)(F2_SA_LO - F2_SA_HI));
                #pragma unroll
                for (int nt = 0; nt < 4; nt++) {
                    uint32_t b0h = bh[(nt >> 1) * 4 + (nt & 1) * 2];
                    uint32_t b1h = bh[(nt >> 1) * 4 + (nt & 1) * 2 + 1];
                    uint32_t b0l = bl[(nt >> 1) * 4 + (nt & 1) * 2];
                    uint32_t b1l = bl[(nt >> 1) * 4 + (nt & 1) * 2 + 1];
                    mma_bf16(c[mt][nt][0], c[mt][nt][1], c[mt][nt][2], c[mt][nt][3],
                             ah[0], ah[1], ah[2], ah[3], b0h, b1h);
                    mma_bf16(c[mt][nt][0], c[mt][nt][1], c[mt][nt][2], c[mt][nt][3],
                             ah[0], ah[1], ah[2], ah[3], b0l, b1l);
                    mma_bf16(c[mt][nt][0], c[mt][nt][1], c[mt][nt][2], c[mt][nt][3],
                             al[0], al[1], al[2], al[3], b0h, b1h);
                }
            }
        }
        if (pass == 0) __syncthreads();
    }

    // ---- epilogue ----
    #pragma unroll
    for (int mt = 0; mt < 2; mt++) {
        int r0 = rowBase + wm * 32 + mt * 16 + g;
        int r1 = r0 + 8;
        #pragma unroll
        for (int nt = 0; nt < 4; nt++) {
            int col = wn * 32 + nt * 8 + tg * 2;
            float b0 = g_bias2[col], b1 = g_bias2[col + 1];
            if (r0 < N_NODES)
                *reinterpret_cast<float2*>(&out[(size_t)r0 * IN_C + col]) =
                    make_float2(c[mt][nt][0] + b0, c[mt][nt][1] + b1);
            if (r1 < N_NODES)
                *reinterpret_cast<float2*>(&out[(size_t)r1 * IN_C + col]) =
                    make_float2(c[mt][nt][2] + b0, c[mt][nt][3] + b1);
        }
    }
}

// ================= launch =================
extern "C" void kernel_launch(void* const* d_in, const int* in_sizes, int n_in,
                              void* d_out, int out_size) {
    const float* x      = nullptr;
    const int*   eidx   = nullptr;
    const float* W_conv = nullptr;
    const float* W_lin  = nullptr;
    const float* b_conv = nullptr;
    const float* b_lin  = nullptr;

    for (int i = 0; i < n_in; i++) {
        int sz = in_sizes[i];
        const void* p = d_in[i];
        if      (sz == N_NODES * IN_C) x = (const float*)p;
        else if (sz == 2 * N_EDGES)    eidx = (const int*)p;
        else if (sz == IN_C * HID) { if (!W_conv) W_conv = (const float*)p;
                                     else         W_lin  = (const float*)p; }
        else if (sz == HID)            b_conv = (const float*)p;
        else if (sz == IN_C)           b_lin  = (const float*)p;
    }
    if (!x || !eidx || !W_conv || !W_lin || !b_conv || !b_lin) {
        x      = (const float*)d_in[0];
        eidx   = (const int*)d_in[1];
        W_conv = (const float*)d_in[2];
        b_conv = (const float*)d_in[3];
        W_lin  = (const float*)d_in[4];
        b_lin  = (const float*)d_in[5];
    }

    float* out = (float*)d_out;
    const int* src = eidx;
    const int* dst = eidx + N_EDGES;

    static bool attr_set = false;
    if (!attr_set) {
        cudaFuncSetAttribute(gemm1_mma, cudaFuncAttributeMaxDynamicSharedMemorySize, G1_SMEM);
        cudaFuncSetAttribute(k_fused2, cudaFuncAttributeMaxDynamicSharedMemorySize, F2_SMEM);
        attr_set = true;
    }

    k_prep1<<<196, 256>>>(W_conv);
    k_prep2<<<64, 256>>>(W_lin, b_conv, b_lin);
    k_count<<<3125, 256>>>(dst);
    gemm1_mma<<<(N_NODES + 127) / 128, 1024, G1_SMEM>>>(x);   // 4th: profiled

    k_scan1<<<SCAN_NB, SCAN_B>>>();
    k_scan3m<<<SCAN_NB, SCAN_B>>>();
    k_fill<<<3125, 256>>>(src, dst);

    k_fused2<<<(N_NODES + 63) / 64, 512, F2_SMEM>>>(out);
}

// round 15
// speedup vs baseline: 1.0743x; 1.0743x over previous
#include <cuda_runtime.h>
#include <cuda_bf16.h>
#include <cstdint>

#define N_NODES 50000
#define IN_C    256
#define HID     128
#define N_EDGES 800000
#define SCAN_B  256
#define SCAN_NB ((N_NODES + SCAN_B - 1) / SCAN_B)   // 196

// ---- device scratch: referenced ONLY from device code ----
__device__ float g_hs[N_NODES * HID];      // h = x @ W_conv (raw)
__device__ int   g_count[N_NODES];
__device__ int   g_rowptr[N_NODES + 1];
__device__ int   g_cursor[N_NODES];
__device__ int   g_col[N_EDGES];
__device__ float g_dinv[N_NODES];
__device__ float g_bias2[IN_C];
__device__ int   g_blocksum[SCAN_NB];
__device__ __nv_bfloat16 g_wchi[HID * IN_C];   // W_conv^T [n][k]
__device__ __nv_bfloat16 g_wclo[HID * IN_C];
__device__ __nv_bfloat16 g_wlhi[IN_C * HID];   // W_lin^T  [n][k]
__device__ __nv_bfloat16 g_wllo[IN_C * HID];

// ================= helpers =================
__device__ __forceinline__ uint32_t pack_bf16(float a, float b) {
    __nv_bfloat16 ha = __float2bfloat16(a);
    __nv_bfloat16 hb = __float2bfloat16(b);
    uint16_t ua = *reinterpret_cast<uint16_t*>(&ha);
    uint16_t ub = *reinterpret_cast<uint16_t*>(&hb);
    return (uint32_t)ua | ((uint32_t)ub << 16);
}
__device__ __forceinline__ float bf16_residual(float v) {
    __nv_bfloat16 h = __float2bfloat16(v);
    return v - __bfloat162float(h);
}
__device__ __forceinline__ void mma_bf16(float& c0, float& c1, float& c2, float& c3,
                                         uint32_t a0, uint32_t a1, uint32_t a2, uint32_t a3,
                                         uint32_t b0, uint32_t b1) {
    asm volatile(
        "mma.sync.aligned.m16n8k16.row.col.f32.bf16.bf16.f32 "
        "{%0,%1,%2,%3}, {%4,%5,%6,%7}, {%8,%9}, {%0,%1,%2,%3};"
        : "+f"(c0), "+f"(c1), "+f"(c2), "+f"(c3)
        : "r"(a0), "r"(a1), "r"(a2), "r"(a3), "r"(b0), "r"(b1));
}
__device__ __forceinline__ uint32_t smem_addr_u32(const void* p) {
    uint32_t a;
    asm("{ .reg .u64 t; cvta.to.shared.u64 t, %1; cvt.u32.u64 %0, t; }" : "=r"(a) : "l"(p));
    return a;
}
__device__ __forceinline__ void ldmx4(uint32_t& r0, uint32_t& r1, uint32_t& r2, uint32_t& r3,
                                      uint32_t addr) {
    asm volatile("ldmatrix.sync.aligned.m8n8.x4.shared.b16 {%0,%1,%2,%3}, [%4];"
                 : "=r"(r0), "=r"(r1), "=r"(r2), "=r"(r3) : "r"(addr));
}
#define GROUP_BAR(id) asm volatile("bar.sync %0, 128;" :: "r"(id) : "memory")

// ================= prep =================
__global__ void k_prep1(const float* __restrict__ W_conv) {   // W_conv split + zero count
    for (int i = blockIdx.x * blockDim.x + threadIdx.x; i < IN_C * HID;
         i += gridDim.x * blockDim.x) {
        int k = i / HID, n = i % HID;
        float v = W_conv[i];
        g_wchi[n * IN_C + k] = __float2bfloat16(v);
        g_wclo[n * IN_C + k] = __float2bfloat16(bf16_residual(v));
    }
    for (int i = blockIdx.x * blockDim.x + threadIdx.x; i < N_NODES;
         i += gridDim.x * blockDim.x)
        g_count[i] = 0;
}

__global__ void k_prep2(const float* __restrict__ W_lin,      // W_lin split + bias2
                        const float* __restrict__ b_conv,
                        const float* __restrict__ b_lin) {
    int gt = blockIdx.x * blockDim.x + threadIdx.x;
    for (int i = gt; i < HID * IN_C; i += gridDim.x * blockDim.x) {
        int k = i / IN_C, n = i % IN_C;
        float v = W_lin[i];
        g_wlhi[n * HID + k] = __float2bfloat16(v);
        g_wllo[n * HID + k] = __float2bfloat16(bf16_residual(v));
    }
    if (gt < IN_C) {
        float s = b_lin[gt];
        #pragma unroll 4
        for (int k = 0; k < HID; k++) s += b_conv[k] * W_lin[k * IN_C + gt];
        g_bias2[gt] = s;
    }
}

// ================= GEMM1: 1024 thr, smem A + ldmatrix, GROUP-LOCAL barriers =================
#define W_STRIDE 264                         // bf16 per W smem row (528B)
#define SW_HI    0
#define SW_LO    (HID * W_STRIDE * 2)        // 67584
#define SA_BASE  (2 * HID * W_STRIDE * 2)    // 135168
#define A_STRIDE 48
#define A_HALF   (128 * A_STRIDE)            // 6144
#define SA_BUF   (2 * A_HALF)                // 12288
#define G1_SMEM  (SA_BASE + 2 * SA_BUF)      // 159744

__global__ __launch_bounds__(1024, 1)
void gemm1_mma(const float* __restrict__ x) {
    extern __shared__ char smem[];
    const uint32_t sb = smem_addr_u32(smem);
    const int tid  = threadIdx.x;
    const int wid  = tid >> 5;        // 0..31
    const int lane = tid & 31;
    const int g    = lane >> 2;
    const int tg   = lane & 3;
    const int wm   = wid >> 2;        // 0..7 -> 16-row strip (group of 4 warps)
    const int wn   = wid & 3;         // 0..3 -> 32-col strip
    const int rowBase = blockIdx.x * 128;

    // stage W^T hi/lo (once, whole block)
    for (int idx = tid; idx < 128 * 32; idx += 1024) {
        int n = idx >> 5;
        int q = idx & 31;
        *reinterpret_cast<uint4*>(smem + SW_HI + n * (W_STRIDE * 2) + q * 16) =
            *reinterpret_cast<const uint4*>(&g_wchi[n * IN_C + q * 8]);
        *reinterpret_cast<uint4*>(smem + SW_LO + n * (W_STRIDE * 2) + q * 16) =
            *reinterpret_cast<const uint4*>(&g_wclo[n * IN_C + q * 8]);
    }

    // ---- ldmatrix per-thread addresses ----
    const int lj = lane >> 3;                 // matrix index 0..3
    const int lr = lane & 7;                  // row within matrix
    const uint32_t aAddr0 = sb + SA_BASE +
        (uint32_t)((wm * 16 + (lj & 1) * 8 + lr) * A_STRIDE + (lj >> 1) * 16);
    uint32_t bAddr[2];
    #pragma unroll
    for (int p = 0; p < 2; p++)
        bAddr[p] = sb + SW_HI +
            (uint32_t)((wn * 32 + p * 16 + (lj >> 1) * 8 + lr) * (W_STRIDE * 2) +
                       (lj & 1) * 16);

    // ---- A staging: GROUP-LOCAL. Group wm's 128 threads stage rows wm*16..wm*16+15.
    const int lt = tid & 127;                 // thread within group
    const int rA = wm * 16 + (lt >> 3);       // row this thread stages
    const int q2 = lt & 7;                    // float2 index within 16-k chunk
    const int grow = rowBase + rA;
    const bool valid = (grow < N_NODES);
    const float* xrow = x + (size_t)grow * IN_C + q2 * 2;
    const int sa_off = rA * A_STRIDE + q2 * 4;
    const int barid = wm + 1;                 // named barriers 1..8

    // prologue: chunk 0 -> buf 0
    {
        float2 f = make_float2(0.f, 0.f);
        if (valid) f = *reinterpret_cast<const float2*>(xrow);
        *reinterpret_cast<uint32_t*>(smem + SA_BASE + sa_off) = pack_bf16(f.x, f.y);
        *reinterpret_cast<uint32_t*>(smem + SA_BASE + A_HALF + sa_off) =
            pack_bf16(bf16_residual(f.x), bf16_residual(f.y));
    }

    float c[4][4];
    #pragma unroll
    for (int nt = 0; nt < 4; nt++)
        #pragma unroll
        for (int q = 0; q < 4; q++) c[nt][q] = 0.0f;

    __syncthreads();    // W + prologue A visible to all

    for (int kc = 0; kc < 16; kc++) {
        const int p = kc & 1;
        const uint32_t aBuf = aAddr0 + (uint32_t)(p * SA_BUF);

        // prefetch next chunk
        float2 nf = make_float2(0.f, 0.f);
        if (kc < 15 && valid)
            nf = *reinterpret_cast<const float2*>(xrow + (kc + 1) * 16);

        // A fragments hi/lo via ldmatrix.x4
        uint32_t ah[4], al[4];
        ldmx4(ah[0], ah[1], ah[2], ah[3], aBuf);
        ldmx4(al[0], al[1], al[2], al[3], aBuf + A_HALF);

        // B pairs + MMAs
        #pragma unroll
        for (int pr = 0; pr < 2; pr++) {
            uint32_t bh[4], bl[4];
            uint32_t ba = bAddr[pr] + (uint32_t)(kc * 32);
            ldmx4(bh[0], bh[1], bh[2], bh[3], ba);
            ldmx4(bl[0], bl[1], bl[2], bl[3], ba + (uint32_t)(SW_LO - SW_HI));
            #pragma unroll
            for (int s = 0; s < 2; s++) {
                int nt = pr * 2 + s;
                mma_bf16(c[nt][0], c[nt][1], c[nt][2], c[nt][3],
                         ah[0], ah[1], ah[2], ah[3], bh[s * 2], bh[s * 2 + 1]);
                mma_bf16(c[nt][0], c[nt][1], c[nt][2], c[nt][3],
                         ah[0], ah[1], ah[2], ah[3], bl[s * 2], bl[s * 2 + 1]);
                mma_bf16(c[nt][0], c[nt][1], c[nt][2], c[nt][3],
                         al[0], al[1], al[2], al[3], bh[s * 2], bh[s * 2 + 1]);
            }
        }

        // stage prefetched chunk into other buffer; group-local barrier only
        if (kc < 15) {
            char* nbuf = smem + SA_BASE + (1 - p) * SA_BUF;
            *reinterpret_cast<uint32_t*>(nbuf + sa_off) = pack_bf16(nf.x, nf.y);
            *reinterpret_cast<uint32_t*>(nbuf + A_HALF + sa_off) =
                pack_bf16(bf16_residual(nf.x), bf16_residual(nf.y));
            GROUP_BAR(barid);
        }
    }

    // epilogue
    {
        int r0 = rowBase + wm * 16 + g;
        int r1 = r0 + 8;
        #pragma unroll
        for (int nt = 0; nt < 4; nt++) {
            int col = wn * 32 + nt * 8 + tg * 2;
            if (r0 < N_NODES)
                *reinterpret_cast<float2*>(&g_hs[(size_t)r0 * HID + col]) =
                    make_float2(c[nt][0], c[nt][1]);
            if (r1 < N_NODES)
                *reinterpret_cast<float2*>(&g_hs[(size_t)r1 * HID + col]) =
                    make_float2(c[nt][2], c[nt][3]);
        }
    }
}

// ================= CSR build =================
__global__ void k_count(const int* __restrict__ dst) {
    for (int e = blockIdx.x * blockDim.x + threadIdx.x; e < N_EDGES;
         e += gridDim.x * blockDim.x)
        atomicAdd(&g_count[dst[e]], 1);
}

__global__ void k_scan1() {
    __shared__ int sh[SCAN_B];
    int i = blockIdx.x * SCAN_B + threadIdx.x;
    int v = (i < N_NODES) ? g_count[i] : 0;
    sh[threadIdx.x] = v;
    __syncthreads();
    #pragma unroll
    for (int o = 1; o < SCAN_B; o <<= 1) {
        int t = (threadIdx.x >= o) ? sh[threadIdx.x - o] : 0;
        __syncthreads();
        sh[threadIdx.x] += t;
        __syncthreads();
    }
    if (i < N_NODES) g_rowptr[i] = sh[threadIdx.x] - v;
    if (threadIdx.x == SCAN_B - 1) g_blocksum[blockIdx.x] = sh[SCAN_B - 1];
}

__global__ void k_scan3m() {
    __shared__ int sh[256];
    const int bid = blockIdx.x;
    const int t = threadIdx.x;
    sh[t] = (t < SCAN_NB && t < bid) ? g_blocksum[t] : 0;
    __syncthreads();
    #pragma unroll
    for (int s = 128; s > 0; s >>= 1) {
        if (t < s) sh[t] += sh[t + s];
        __syncthreads();
    }
    const int off = sh[0];
    int i = bid * SCAN_B + t;
    if (i < N_NODES) {
        int r = g_rowptr[i] + off;
        g_rowptr[i] = r;
        g_cursor[i] = r;
        g_dinv[i]   = rsqrtf((float)(g_count[i] + 1));
    }
    if (bid == 0 && t == 0) g_rowptr[N_NODES] = N_EDGES;
}

__global__ void k_fill(const int* __restrict__ src, const int* __restrict__ dst) {
    for (int e = blockIdx.x * blockDim.x + threadIdx.x; e < N_EDGES;
         e += gridDim.x * blockDim.x) {
        int p = atomicAdd(&g_cursor[dst[e]], 1);
        g_col[p] = src[e];
    }
}

// ================= FUSED gather + HMMA GEMM2 (ldmatrix, from R14) =================
#define F2_PAD   272
#define F2_WPAD  144
#define F2_SA_HI 0
#define F2_SA_LO (64 * F2_PAD)                  // 17408
#define F2_SW_HI (2 * 64 * F2_PAD)              // 34816
#define F2_SW_LO (F2_SW_HI + 256 * F2_WPAD)     // 71680
#define F2_SMEM  (F2_SW_LO + 256 * F2_WPAD)     // 108544

__global__ __launch_bounds__(512, 2)
void k_fused2(float* __restrict__ out) {
    extern __shared__ char smem[];
    const uint32_t sb = smem_addr_u32(smem);
    const int tid = threadIdx.x;
    const int w   = tid >> 5;
    const int l   = tid & 31;
    const int rowBase = blockIdx.x * 64;

    // ---- gather 64 nodes (4 per warp) ----
    const float4* hs4 = reinterpret_cast<const float4*>(g_hs);
    #pragma unroll
    for (int q = 0; q < 4; q++) {
        int nLocal = q * 16 + w;
        int i = rowBase + nLocal;
        float4 acc = make_float4(0.f, 0.f, 0.f, 0.f);
        if (i < N_NODES) {
            float di = g_dinv[i];
            float4 v = hs4[(size_t)i * 32 + l];
            acc.x = v.x * di; acc.y = v.y * di; acc.z = v.z * di; acc.w = v.w * di;
            int e  = g_rowptr[i];
            int e1 = g_rowptr[i + 1];
            for (; e + 2 <= e1; e += 2) {
                int j0 = g_col[e];
                int j1 = g_col[e + 1];
                float d0 = g_dinv[j0];
                float d1 = g_dinv[j1];
                float4 u0 = hs4[(size_t)j0 * 32 + l];
                float4 u1 = hs4[(size_t)j1 * 32 + l];
                acc.x += u0.x * d0 + u1.x * d1;
                acc.y += u0.y * d0 + u1.y * d1;
                acc.z += u0.z * d0 + u1.z * d1;
                acc.w += u0.w * d0 + u1.w * d1;
            }
            if (e < e1) {
                int j = g_col[e];
                float dj = g_dinv[j];
                float4 u = hs4[(size_t)j * 32 + l];
                acc.x += u.x * dj; acc.y += u.y * dj;
                acc.z += u.z * dj; acc.w += u.w * dj;
            }
            acc.x *= di; acc.y *= di; acc.z *= di; acc.w *= di;
        }
        uint2 hi, lo;
        hi.x = pack_bf16(acc.x, acc.y);
        hi.y = pack_bf16(acc.z, acc.w);
        lo.x = pack_bf16(bf16_residual(acc.x), bf16_residual(acc.y));
        lo.y = pack_bf16(bf16_residual(acc.z), bf16_residual(acc.w));
        *reinterpret_cast<uint2*>(smem + F2_SA_HI + nLocal * F2_PAD + l * 8) = hi;
        *reinterpret_cast<uint2*>(smem + F2_SA_LO + nLocal * F2_PAD + l * 8) = lo;
    }
    __syncthreads();

    // ---- HMMA: out[64,256] = agg @ W_lin, K split into two 64-wide passes ----
    const int g  = l >> 2;
    const int tg = l & 3;
    const int wm = w >> 3;            // 0..1
    const int wn = w & 7;             // 0..7
    const int lj = l >> 3;
    const int lr = l & 7;

    const uint32_t aAddrF = sb + F2_SA_HI +
        (uint32_t)((wm * 32 + (lj & 1) * 8 + lr) * F2_PAD + (lj >> 1) * 16);
    uint32_t bAddrF[2];
    #pragma unroll
    for (int p = 0; p < 2; p++)
        bAddrF[p] = sb + F2_SW_HI +
            (uint32_t)((wn * 32 + p * 16 + (lj >> 1) * 8 + lr) * F2_WPAD + (lj & 1) * 16);

    float c[2][4][4];
    #pragma unroll
    for (int mt = 0; mt < 2; mt++)
        #pragma unroll
        for (int nt = 0; nt < 4; nt++)
            #pragma unroll
            for (int q = 0; q < 4; q++) c[mt][nt][q] = 0.0f;

    #pragma unroll
    for (int pass = 0; pass < 2; pass++) {
        for (int idx = tid; idx < 256 * 8; idx += 512) {
            int n  = idx >> 3;
            int q8 = idx & 7;
            *reinterpret_cast<uint4*>(smem + F2_SW_HI + n * F2_WPAD + q8 * 16) =
                *reinterpret_cast<const uint4*>(&g_wlhi[n * HID + pass * 64 + q8 * 8]);
            *reinterpret_cast<uint4*>(smem + F2_SW_LO + n * F2_WPAD + q8 * 16) =
                *reinterpret_cast<const uint4*>(&g_wllo[n * HID + pass * 64 + q8 * 8]);
        }
        __syncthreads();

        #pragma unroll
        for (int kc = 0; kc < 4; kc++) {
            uint32_t bh[8], bl[8];
            #pragma unroll
            for (int pr = 0; pr < 2; pr++) {
                uint32_t ba = bAddrF[pr] + (uint32_t)(kc * 32);
                ldmx4(bh[pr * 4 + 0], bh[pr * 4 + 1], bh[pr * 4 + 2], bh[pr * 4 + 3], ba);
                ldmx4(bl[pr * 4 + 0], bl[pr * 4 + 1], bl[pr * 4 + 2], bl[pr * 4 + 3],
                      ba + (uint32_t)(F2_SW_LO - F2_SW_HI));
            }
            #pragma unroll
            for (int mt = 0; mt < 2; mt++) {
                uint32_t aa = aAddrF + (uint32_t)(mt * 16 * F2_PAD + pass * 128 + kc * 32);
                uint32_t ah[4], al[4];
                ldmx4(ah[0], ah[1], ah[2], ah[3], aa);
                ldmx4(al[0], al[1], al[2], al[3], aa + (uint32_t)(F2_SA_LO - F2_SA_HI));
                #pragma unroll
                for (int nt = 0; nt < 4; nt++) {
                    uint32_t b0h = bh[(nt >> 1) * 4 + (nt & 1) * 2];
                    uint32_t b1h = bh[(nt >> 1) * 4 + (nt & 1) * 2 + 1];
                    uint32_t b0l = bl[(nt >> 1) * 4 + (nt & 1) * 2];
                    uint32_t b1l = bl[(nt >> 1) * 4 + (nt & 1) * 2 + 1];
                    mma_bf16(c[mt][nt][0], c[mt][nt][1], c[mt][nt][2], c[mt][nt][3],
                             ah[0], ah[1], ah[2], ah[3], b0h, b1h);
                    mma_bf16(c[mt][nt][0], c[mt][nt][1], c[mt][nt][2], c[mt][nt][3],
                             ah[0], ah[1], ah[2], ah[3], b0l, b1l);
                    mma_bf16(c[mt][nt][0], c[mt][nt][1], c[mt][nt][2], c[mt][nt][3],
                             al[0], al[1], al[2], al[3], b0h, b1h);
                }
            }
        }
        if (pass == 0) __syncthreads();
    }

    // ---- epilogue ----
    #pragma unroll
    for (int mt = 0; mt < 2; mt++) {
        int r0 = rowBase + wm * 32 + mt * 16 + g;
        int r1 = r0 + 8;
        #pragma unroll
        for (int nt = 0; nt < 4; nt++) {
            int col = wn * 32 + nt * 8 + tg * 2;
            float b0 = g_bias2[col], b1 = g_bias2[col + 1];
            if (r0 < N_NODES)
                *reinterpret_cast<float2*>(&out[(size_t)r0 * IN_C + col]) =
                    make_float2(c[mt][nt][0] + b0, c[mt][nt][1] + b1);
            if (r1 < N_NODES)
                *reinterpret_cast<float2*>(&out[(size_t)r1 * IN_C + col]) =
                    make_float2(c[mt][nt][2] + b0, c[mt][nt][3] + b1);
        }
    }
}

// ================= launch =================
extern "C" void kernel_launch(void* const* d_in, const int* in_sizes, int n_in,
                              void* d_out, int out_size) {
    const float* x      = nullptr;
    const int*   eidx   = nullptr;
    const float* W_conv = nullptr;
    const float* W_lin  = nullptr;
    const float* b_conv = nullptr;
    const float* b_lin  = nullptr;

    for (int i = 0; i < n_in; i++) {
        int sz = in_sizes[i];
        const void* p = d_in[i];
        if      (sz == N_NODES * IN_C) x = (const float*)p;
        else if (sz == 2 * N_EDGES)    eidx = (const int*)p;
        else if (sz == IN_C * HID) { if (!W_conv) W_conv = (const float*)p;
                                     else         W_lin  = (const float*)p; }
        else if (sz == HID)            b_conv = (const float*)p;
        else if (sz == IN_C)           b_lin  = (const float*)p;
    }
    if (!x || !eidx || !W_conv || !W_lin || !b_conv || !b_lin) {
        x      = (const float*)d_in[0];
        eidx   = (const int*)d_in[1];
        W_conv = (const float*)d_in[2];
        b_conv = (const float*)d_in[3];
        W_lin  = (const float*)d_in[4];
        b_lin  = (const float*)d_in[5];
    }

    float* out = (float*)d_out;
    const int* src = eidx;
    const int* dst = eidx + N_EDGES;

    static bool attr_set = false;
    if (!attr_set) {
        cudaFuncSetAttribute(gemm1_mma, cudaFuncAttributeMaxDynamicSharedMemorySize, G1_SMEM);
        cudaFuncSetAttribute(k_fused2, cudaFuncAttributeMaxDynamicSharedMemorySize, F2_SMEM);
        attr_set = true;
    }

    k_prep1<<<196, 256>>>(W_conv);
    k_prep2<<<64, 256>>>(W_lin, b_conv, b_lin);
    k_count<<<3125, 256>>>(dst);
    gemm1_mma<<<(N_NODES + 127) / 128, 1024, G1_SMEM>>>(x);   // 4th: profiled

    k_scan1<<<SCAN_NB, SCAN_B>>>();
    k_scan3m<<<SCAN_NB, SCAN_B>>>();
    k_fill<<<3125, 256>>>(src, dst);

    k_fused2<<<(N_NODES + 63) / 64, 512, F2_SMEM>>>(out);
}

// round 16
// speedup vs baseline: 1.1399x; 1.0611x over previous
#include <cuda_runtime.h>
#include <cuda_bf16.h>
#include <cuda_fp16.h>
#include <cstdint>

#define N_NODES 50000
#define IN_C    256
#define HID     128
#define N_EDGES 800000
#define SCAN_B  256
#define SCAN_NB ((N_NODES + SCAN_B - 1) / SCAN_B)   // 196

// ---- device scratch: referenced ONLY from device code ----
__device__ __half g_hs16[N_NODES * HID];   // p = (x @ W_conv) * dinv[row], fp16
__device__ int   g_count[N_NODES];
__device__ int   g_rowptr[N_NODES + 1];
__device__ int   g_cursor[N_NODES];
__device__ int   g_col[N_EDGES];
__device__ float g_dinv[N_NODES];
__device__ float g_bias2[IN_C];
__device__ int   g_blocksum[SCAN_NB];
__device__ __nv_bfloat16 g_wchi[HID * IN_C];   // W_conv^T [n][k]
__device__ __nv_bfloat16 g_wclo[HID * IN_C];
__device__ __nv_bfloat16 g_wlhi[IN_C * HID];   // W_lin^T  [n][k]
__device__ __nv_bfloat16 g_wllo[IN_C * HID];

// ================= helpers =================
__device__ __forceinline__ uint32_t pack_bf16(float a, float b) {
    __nv_bfloat16 ha = __float2bfloat16(a);
    __nv_bfloat16 hb = __float2bfloat16(b);
    uint16_t ua = *reinterpret_cast<uint16_t*>(&ha);
    uint16_t ub = *reinterpret_cast<uint16_t*>(&hb);
    return (uint32_t)ua | ((uint32_t)ub << 16);
}
__device__ __forceinline__ float bf16_residual(float v) {
    __nv_bfloat16 h = __float2bfloat16(v);
    return v - __bfloat162float(h);
}
__device__ __forceinline__ void mma_bf16(float& c0, float& c1, float& c2, float& c3,
                                         uint32_t a0, uint32_t a1, uint32_t a2, uint32_t a3,
                                         uint32_t b0, uint32_t b1) {
    asm volatile(
        "mma.sync.aligned.m16n8k16.row.col.f32.bf16.bf16.f32 "
        "{%0,%1,%2,%3}, {%4,%5,%6,%7}, {%8,%9}, {%0,%1,%2,%3};"
        : "+f"(c0), "+f"(c1), "+f"(c2), "+f"(c3)
        : "r"(a0), "r"(a1), "r"(a2), "r"(a3), "r"(b0), "r"(b1));
}
__device__ __forceinline__ uint32_t smem_addr_u32(const void* p) {
    uint32_t a;
    asm("{ .reg .u64 t; cvta.to.shared.u64 t, %1; cvt.u32.u64 %0, t; }" : "=r"(a) : "l"(p));
    return a;
}
__device__ __forceinline__ void ldmx4(uint32_t& r0, uint32_t& r1, uint32_t& r2, uint32_t& r3,
                                      uint32_t addr) {
    asm volatile("ldmatrix.sync.aligned.m8n8.x4.shared.b16 {%0,%1,%2,%3}, [%4];"
                 : "=r"(r0), "=r"(r1), "=r"(r2), "=r"(r3) : "r"(addr));
}
#define GROUP_BAR(id) asm volatile("bar.sync %0, 128;" :: "r"(id) : "memory")

// ================= prep =================
__global__ void k_prep1(const float* __restrict__ W_conv) {   // W_conv split + zero count
    for (int i = blockIdx.x * blockDim.x + threadIdx.x; i < IN_C * HID;
         i += gridDim.x * blockDim.x) {
        int k = i / HID, n = i % HID;
        float v = W_conv[i];
        g_wchi[n * IN_C + k] = __float2bfloat16(v);
        g_wclo[n * IN_C + k] = __float2bfloat16(bf16_residual(v));
    }
    for (int i = blockIdx.x * blockDim.x + threadIdx.x; i < N_NODES;
         i += gridDim.x * blockDim.x)
        g_count[i] = 0;
}

__global__ void k_prep2(const float* __restrict__ W_lin,      // W_lin split + bias2
                        const float* __restrict__ b_conv,
                        const float* __restrict__ b_lin) {
    int gt = blockIdx.x * blockDim.x + threadIdx.x;
    for (int i = gt; i < HID * IN_C; i += gridDim.x * blockDim.x) {
        int k = i / IN_C, n = i % IN_C;
        float v = W_lin[i];
        g_wlhi[n * HID + k] = __float2bfloat16(v);
        g_wllo[n * HID + k] = __float2bfloat16(bf16_residual(v));
    }
    if (gt < IN_C) {
        float s = b_lin[gt];
        #pragma unroll 4
        for (int k = 0; k < HID; k++) s += b_conv[k] * W_lin[k * IN_C + gt];
        g_bias2[gt] = s;
    }
}

// ================= CSR build =================
__global__ void k_count(const int* __restrict__ dst) {
    for (int e = blockIdx.x * blockDim.x + threadIdx.x; e < N_EDGES;
         e += gridDim.x * blockDim.x)
        atomicAdd(&g_count[dst[e]], 1);
}

__global__ void k_scan1() {
    __shared__ int sh[SCAN_B];
    int i = blockIdx.x * SCAN_B + threadIdx.x;
    int v = (i < N_NODES) ? g_count[i] : 0;
    sh[threadIdx.x] = v;
    __syncthreads();
    #pragma unroll
    for (int o = 1; o < SCAN_B; o <<= 1) {
        int t = (threadIdx.x >= o) ? sh[threadIdx.x - o] : 0;
        __syncthreads();
        sh[threadIdx.x] += t;
        __syncthreads();
    }
    if (i < N_NODES) g_rowptr[i] = sh[threadIdx.x] - v;
    if (threadIdx.x == SCAN_B - 1) g_blocksum[blockIdx.x] = sh[SCAN_B - 1];
}

__global__ void k_scan3m() {
    __shared__ int sh[256];
    const int bid = blockIdx.x;
    const int t = threadIdx.x;
    sh[t] = (t < SCAN_NB && t < bid) ? g_blocksum[t] : 0;
    __syncthreads();
    #pragma unroll
    for (int s = 128; s > 0; s >>= 1) {
        if (t < s) sh[t] += sh[t + s];
        __syncthreads();
    }
    const int off = sh[0];
    int i = bid * SCAN_B + t;
    if (i < N_NODES) {
        int r = g_rowptr[i] + off;
        g_rowptr[i] = r;
        g_cursor[i] = r;
        g_dinv[i]   = rsqrtf((float)(g_count[i] + 1));
    }
    if (bid == 0 && t == 0) g_rowptr[N_NODES] = N_EDGES;
}

__global__ void k_fill(const int* __restrict__ src, const int* __restrict__ dst) {
    for (int e = blockIdx.x * blockDim.x + threadIdx.x; e < N_EDGES;
         e += gridDim.x * blockDim.x) {
        int p = atomicAdd(&g_cursor[dst[e]], 1);
        g_col[p] = src[e];
    }
}

// ================= GEMM1: 1024 thr, smem A + ldmatrix, group barriers =================
// writes g_hs16 = (x @ W_conv) * dinv[row] as fp16
#define W_STRIDE 264                         // bf16 per W smem row (528B)
#define SW_HI    0
#define SW_LO    (HID * W_STRIDE * 2)        // 67584
#define SA_BASE  (2 * HID * W_STRIDE * 2)    // 135168
#define A_STRIDE 48
#define A_HALF   (128 * A_STRIDE)            // 6144
#define SA_BUF   (2 * A_HALF)                // 12288
#define G1_SMEM  (SA_BASE + 2 * SA_BUF)      // 159744

__global__ __launch_bounds__(1024, 1)
void gemm1_mma(const float* __restrict__ x) {
    extern __shared__ char smem[];
    const uint32_t sb = smem_addr_u32(smem);
    const int tid  = threadIdx.x;
    const int wid  = tid >> 5;        // 0..31
    const int lane = tid & 31;
    const int g    = lane >> 2;
    const int tg   = lane & 3;
    const int wm   = wid >> 2;        // 0..7 -> 16-row strip
    const int wn   = wid & 3;         // 0..3 -> 32-col strip
    const int rowBase = blockIdx.x * 128;

    for (int idx = tid; idx < 128 * 32; idx += 1024) {
        int n = idx >> 5;
        int q = idx & 31;
        *reinterpret_cast<uint4*>(smem + SW_HI + n * (W_STRIDE * 2) + q * 16) =
            *reinterpret_cast<const uint4*>(&g_wchi[n * IN_C + q * 8]);
        *reinterpret_cast<uint4*>(smem + SW_LO + n * (W_STRIDE * 2) + q * 16) =
            *reinterpret_cast<const uint4*>(&g_wclo[n * IN_C + q * 8]);
    }

    const int lj = lane >> 3;
    const int lr = lane & 7;
    const uint32_t aAddr0 = sb + SA_BASE +
        (uint32_t)((wm * 16 + (lj & 1) * 8 + lr) * A_STRIDE + (lj >> 1) * 16);
    uint32_t bAddr[2];
    #pragma unroll
    for (int p = 0; p < 2; p++)
        bAddr[p] = sb + SW_HI +
            (uint32_t)((wn * 32 + p * 16 + (lj >> 1) * 8 + lr) * (W_STRIDE * 2) +
                       (lj & 1) * 16);

    const int lt = tid & 127;
    const int rA = wm * 16 + (lt >> 3);
    const int q2 = lt & 7;
    const int grow = rowBase + rA;
    const bool valid = (grow < N_NODES);
    const float* xrow = x + (size_t)grow * IN_C + q2 * 2;
    const int sa_off = rA * A_STRIDE + q2 * 4;
    const int barid = wm + 1;

    {
        float2 f = make_float2(0.f, 0.f);
        if (valid) f = *reinterpret_cast<const float2*>(xrow);
        *reinterpret_cast<uint32_t*>(smem + SA_BASE + sa_off) = pack_bf16(f.x, f.y);
        *reinterpret_cast<uint32_t*>(smem + SA_BASE + A_HALF + sa_off) =
            pack_bf16(bf16_residual(f.x), bf16_residual(f.y));
    }

    float c[4][4];
    #pragma unroll
    for (int nt = 0; nt < 4; nt++)
        #pragma unroll
        for (int q = 0; q < 4; q++) c[nt][q] = 0.0f;

    __syncthreads();

    for (int kc = 0; kc < 16; kc++) {
        const int p = kc & 1;
        const uint32_t aBuf = aAddr0 + (uint32_t)(p * SA_BUF);

        float2 nf = make_float2(0.f, 0.f);
        if (kc < 15 && valid)
            nf = *reinterpret_cast<const float2*>(xrow + (kc + 1) * 16);

        uint32_t ah[4], al[4];
        ldmx4(ah[0], ah[1], ah[2], ah[3], aBuf);
        ldmx4(al[0], al[1], al[2], al[3], aBuf + A_HALF);

        #pragma unroll
        for (int pr = 0; pr < 2; pr++) {
            uint32_t bh[4], bl[4];
            uint32_t ba = bAddr[pr] + (uint32_t)(kc * 32);
            ldmx4(bh[0], bh[1], bh[2], bh[3], ba);
            ldmx4(bl[0], bl[1], bl[2], bl[3], ba + (uint32_t)(SW_LO - SW_HI));
            #pragma unroll
            for (int s = 0; s < 2; s++) {
                int nt = pr * 2 + s;
                mma_bf16(c[nt][0], c[nt][1], c[nt][2], c[nt][3],
                         ah[0], ah[1], ah[2], ah[3], bh[s * 2], bh[s * 2 + 1]);
                mma_bf16(c[nt][0], c[nt][1], c[nt][2], c[nt][3],
                         ah[0], ah[1], ah[2], ah[3], bl[s * 2], bl[s * 2 + 1]);
                mma_bf16(c[nt][0], c[nt][1], c[nt][2], c[nt][3],
                         al[0], al[1], al[2], al[3], bh[s * 2], bh[s * 2 + 1]);
            }
        }

        if (kc < 15) {
            char* nbuf = smem + SA_BASE + (1 - p) * SA_BUF;
            *reinterpret_cast<uint32_t*>(nbuf + sa_off) = pack_bf16(nf.x, nf.y);
            *reinterpret_cast<uint32_t*>(nbuf + A_HALF + sa_off) =
                pack_bf16(bf16_residual(nf.x), bf16_residual(nf.y));
            GROUP_BAR(barid);
        }
    }

    // epilogue: scale by dinv[row], convert to fp16, store
    {
        int r0 = rowBase + wm * 16 + g;
        int r1 = r0 + 8;
        float dv0 = (r0 < N_NODES) ? g_dinv[r0] : 0.0f;
        float dv1 = (r1 < N_NODES) ? g_dinv[r1] : 0.0f;
        #pragma unroll
        for (int nt = 0; nt < 4; nt++) {
            int col = wn * 32 + nt * 8 + tg * 2;
            if (r0 < N_NODES) {
                __half2 h2 = __floats2half2_rn(c[nt][0] * dv0, c[nt][1] * dv0);
                *reinterpret_cast<__half2*>(&g_hs16[(size_t)r0 * HID + col]) = h2;
            }
            if (r1 < N_NODES) {
                __half2 h2 = __floats2half2_rn(c[nt][2] * dv1, c[nt][3] * dv1);
                *reinterpret_cast<__half2*>(&g_hs16[(size_t)r1 * HID + col]) = h2;
            }
        }
    }
}

// ================= FUSED gather + HMMA GEMM2 =================
#define F2_PAD   272
#define F2_WPAD  144
#define F2_SA_HI 0
#define F2_SA_LO (64 * F2_PAD)                  // 17408
#define F2_SW_HI (2 * 64 * F2_PAD)              // 34816
#define F2_SW_LO (F2_SW_HI + 256 * F2_WPAD)     // 71680
#define F2_SMEM  (F2_SW_LO + 256 * F2_WPAD)     // 108544

__global__ __launch_bounds__(512, 2)
void k_fused2(float* __restrict__ out) {
    extern __shared__ char smem[];
    const uint32_t sb = smem_addr_u32(smem);
    const int tid = threadIdx.x;
    const int w   = tid >> 5;
    const int l   = tid & 31;
    const int rowBase = blockIdx.x * 64;

    // ---- gather 64 nodes (4 per warp); hs16 rows are pre-scaled by dinv[src] ----
    const uint2* hs8 = reinterpret_cast<const uint2*>(g_hs16);   // 4 halves per uint2
    #pragma unroll
    for (int q = 0; q < 4; q++) {
        int nLocal = q * 16 + w;
        int i = rowBase + nLocal;
        float4 acc = make_float4(0.f, 0.f, 0.f, 0.f);
        if (i < N_NODES) {
            float di = g_dinv[i];
            {   // self: p_i
                uint2 raw = hs8[(size_t)i * 32 + l];
                float2 s0 = __half22float2(*reinterpret_cast<__half2*>(&raw.x));
                float2 s1 = __half22float2(*reinterpret_cast<__half2*>(&raw.y));
                acc.x = s0.x; acc.y = s0.y; acc.z = s1.x; acc.w = s1.y;
            }
            int e  = g_rowptr[i];
            int e1 = g_rowptr[i + 1];
            for (; e + 2 <= e1; e += 2) {
                int j0 = g_col[e];
                int j1 = g_col[e + 1];
                uint2 r0 = hs8[(size_t)j0 * 32 + l];
                uint2 r1 = hs8[(size_t)j1 * 32 + l];
                float2 a0 = __half22float2(*reinterpret_cast<__half2*>(&r0.x));
                float2 a1 = __half22float2(*reinterpret_cast<__half2*>(&r0.y));
                float2 b0 = __half22float2(*reinterpret_cast<__half2*>(&r1.x));
                float2 b1 = __half22float2(*reinterpret_cast<__half2*>(&r1.y));
                acc.x += a0.x + b0.x;
                acc.y += a0.y + b0.y;
                acc.z += a1.x + b1.x;
                acc.w += a1.y + b1.y;
            }
            if (e < e1) {
                int j = g_col[e];
                uint2 r0 = hs8[(size_t)j * 32 + l];
                float2 a0 = __half22float2(*reinterpret_cast<__half2*>(&r0.x));
                float2 a1 = __half22float2(*reinterpret_cast<__half2*>(&r0.y));
                acc.x += a0.x; acc.y += a0.y; acc.z += a1.x; acc.w += a1.y;
            }
            acc.x *= di; acc.y *= di; acc.z *= di; acc.w *= di;
        }
        uint2 hi, lo;
        hi.x = pack_bf16(acc.x, acc.y);
        hi.y = pack_bf16(acc.z, acc.w);
        lo.x = pack_bf16(bf16_residual(acc.x), bf16_residual(acc.y));
        lo.y = pack_bf16(bf16_residual(acc.z), bf16_residual(acc.w));
        *reinterpret_cast<uint2*>(smem + F2_SA_HI + nLocal * F2_PAD + l * 8) = hi;
        *reinterpret_cast<uint2*>(smem + F2_SA_LO + nLocal * F2_PAD + l * 8) = lo;
    }
    __syncthreads();

    // ---- HMMA: out[64,256] = agg @ W_lin, two 64-wide K passes ----
    const int g  = l >> 2;
    const int tg = l & 3;
    const int wm = w >> 3;            // 0..1
    const int wn = w & 7;             // 0..7
    const int lj = l >> 3;
    const int lr = l & 7;

    const uint32_t aAddrF = sb + F2_SA_HI +
        (uint32_t)((wm * 32 + (lj & 1) * 8 + lr) * F2_PAD + (lj >> 1) * 16);
    uint32_t bAddrF[2];
    #pragma unroll
    for (int p = 0; p < 2; p++)
        bAddrF[p] = sb + F2_SW_HI +
            (uint32_t)((wn * 32 + p * 16 + (lj >> 1) * 8 + lr) * F2_WPAD + (lj & 1) * 16);

    float c[2][4][4];
    #pragma unroll
    for (int mt = 0; mt < 2; mt++)
        #pragma unroll
        for (int nt = 0; nt < 4; nt++)
            #pragma unroll
            for (int q = 0; q < 4; q++) c[mt][nt][q] = 0.0f;

    #pragma unroll
    for (int pass = 0; pass < 2; pass++) {
        for (int idx = tid; idx < 256 * 8; idx += 512) {
            int n  = idx >> 3;
            int q8 = idx & 7;
            *reinterpret_cast<uint4*>(smem + F2_SW_HI + n * F2_WPAD + q8 * 16) =
                *reinterpret_cast<const uint4*>(&g_wlhi[n * HID + pass * 64 + q8 * 8]);
            *reinterpret_cast<uint4*>(smem + F2_SW_LO + n * F2_WPAD + q8 * 16) =
                *reinterpret_cast<const uint4*>(&g_wllo[n * HID + pass * 64 + q8 * 8]);
        }
        __syncthreads();

        #pragma unroll
        for (int kc = 0; kc < 4; kc++) {
            uint32_t bh[8], bl[8];
            #pragma unroll
            for (int pr = 0; pr < 2; pr++) {
                uint32_t ba = bAddrF[pr] + (uint32_t)(kc * 32);
                ldmx4(bh[pr * 4 + 0], bh[pr * 4 + 1], bh[pr * 4 + 2], bh[pr * 4 + 3], ba);
                ldmx4(bl[pr * 4 + 0], bl[pr * 4 + 1], bl[pr * 4 + 2], bl[pr * 4 + 3],
                      ba + (uint32_t)(F2_SW_LO - F2_SW_HI));
            }
            #pragma unroll
            for (int mt = 0; mt < 2; mt++) {
                uint32_t aa = aAddrF + (uint32_t)(mt * 16 * F2_PAD + pass * 128 + kc * 32);
                uint32_t ah[4], al[4];
                ldmx4(ah[0], ah[1], ah[2], ah[3], aa);
                ldmx4(al[0], al[1], al[2], al[3], aa + (uint32_t)(F2_SA_LO - F2_SA_HI));
                #pragma unroll
                for (int nt = 0; nt < 4; nt++) {
                    uint32_t b0h = bh[(nt >> 1) * 4 + (nt & 1) * 2];
                    uint32_t b1h = bh[(nt >> 1) * 4 + (nt & 1) * 2 + 1];
                    uint32_t b0l = bl[(nt >> 1) * 4 + (nt & 1) * 2];
                    uint32_t b1l = bl[(nt >> 1) * 4 + (nt & 1) * 2 + 1];
                    mma_bf16(c[mt][nt][0], c[mt][nt][1], c[mt][nt][2], c[mt][nt][3],
                             ah[0], ah[1], ah[2], ah[3], b0h, b1h);
                    mma_bf16(c[mt][nt][0], c[mt][nt][1], c[mt][nt][2], c[mt][nt][3],
                             ah[0], ah[1], ah[2], ah[3], b0l, b1l);
                    mma_bf16(c[mt][nt][0], c[mt][nt][1], c[mt][nt][2], c[mt][nt][3],
                             al[0], al[1], al[2], al[3], b0h, b1h);
                }
            }
        }
        if (pass == 0) __syncthreads();
    }

    // ---- epilogue ----
    #pragma unroll
    for (int mt = 0; mt < 2; mt++) {
        int r0 = rowBase + wm * 32 + mt * 16 + g;
        int r1 = r0 + 8;
        #pragma unroll
        for (int nt = 0; nt < 4; nt++) {
            int col = wn * 32 + nt * 8 + tg * 2;
            float b0 = g_bias2[col], b1 = g_bias2[col + 1];
            if (r0 < N_NODES)
                *reinterpret_cast<float2*>(&out[(size_t)r0 * IN_C + col]) =
                    make_float2(c[mt][nt][0] + b0, c[mt][nt][1] + b1);
            if (r1 < N_NODES)
                *reinterpret_cast<float2*>(&out[(size_t)r1 * IN_C + col]) =
                    make_float2(c[mt][nt][2] + b0, c[mt][nt][3] + b1);
        }
    }
}

// ================= launch =================
extern "C" void kernel_launch(void* const* d_in, const int* in_sizes, int n_in,
                              void* d_out, int out_size) {
    const float* x      = nullptr;
    const int*   eidx   = nullptr;
    const float* W_conv = nullptr;
    const float* W_lin  = nullptr;
    const float* b_conv = nullptr;
    const float* b_lin  = nullptr;

    for (int i = 0; i < n_in; i++) {
        int sz = in_sizes[i];
        const void* p = d_in[i];
        if      (sz == N_NODES * IN_C) x = (const float*)p;
        else if (sz == 2 * N_EDGES)    eidx = (const int*)p;
        else if (sz == IN_C * HID) { if (!W_conv) W_conv = (const float*)p;
                                     else         W_lin  = (const float*)p; }
        else if (sz == HID)            b_conv = (const float*)p;
        else if (sz == IN_C)           b_lin  = (const float*)p;
    }
    if (!x || !eidx || !W_conv || !W_lin || !b_conv || !b_lin) {
        x      = (const float*)d_in[0];
        eidx   = (const int*)d_in[1];
        W_conv = (const float*)d_in[2];
        b_conv = (const float*)d_in[3];
        W_lin  = (const float*)d_in[4];
        b_lin  = (const float*)d_in[5];
    }

    float* out = (float*)d_out;
    const int* src = eidx;
    const int* dst = eidx + N_EDGES;

    static bool attr_set = false;
    if (!attr_set) {
        cudaFuncSetAttribute(gemm1_mma, cudaFuncAttributeMaxDynamicSharedMemorySize, G1_SMEM);
        cudaFuncSetAttribute(k_fused2, cudaFuncAttributeMaxDynamicSharedMemorySize, F2_SMEM);
        attr_set = true;
    }

    // CSR chain first: dinv must be ready before gemm1 (hs16 is dinv-scaled)
    k_prep1<<<196, 256>>>(W_conv);                  // W_conv split + count zero
    k_count<<<3125, 256>>>(dst);
    k_scan1<<<SCAN_NB, SCAN_B>>>();
    k_scan3m<<<SCAN_NB, SCAN_B>>>();                // dinv ready
    k_prep2<<<64, 256>>>(W_lin, b_conv, b_lin);
    k_fill<<<3125, 256>>>(src, dst);
    gemm1_mma<<<(N_NODES + 127) / 128, 1024, G1_SMEM>>>(x);
    k_fused2<<<(N_NODES + 63) / 64, 512, F2_SMEM>>>(out);
}